// round 9
// baseline (speedup 1.0000x reference)
#include <cuda_runtime.h>
#include <cstdint>

// PPRGo via TMA bulk-copy staging.
// out[n,:] = sum_k ( mask(wei[n,k]) / (sum_k mask + 1e-12) ) * emb_table[nei[n,k], :]
// N=200000, TOPK=32, EMB=64. nei int32.
//
// R4's LDG design sits at the L1tex wavefront floor (~128 phases/node:
// 64 demand + 64 data-return). This version gathers each node's 32 rows
// (8 KB) into SMEM with per-lane cp.async.bulk (256 B each, TMA engine,
// no L1 demand/return), mbarrier-completed, then consumes via LDS.128+FMA
// (~64 crossbar phases/node). Tests whether TMA SMEM writes use a port
// separate from the LDS crossbar. Occupancy drops to ~24 warps/SM
// (64 KB staging/block) — latency now hidden by the async copy.

static constexpr int TOPK = 32;
static constexpr int EMB  = 64;
static constexpr int ROW_BYTES  = EMB * (int)sizeof(float);   // 256
static constexpr int NODE_BYTES = TOPK * ROW_BYTES;           // 8192
static constexpr int WARPS_PER_BLOCK = 8;
static constexpr int THREADS = WARPS_PER_BLOCK * 32;
static constexpr int SMEM_DATA  = WARPS_PER_BLOCK * NODE_BYTES;     // 65536
static constexpr int SMEM_TOTAL = SMEM_DATA + WARPS_PER_BLOCK * 8;  // + mbarriers

__device__ __forceinline__ unsigned smem_u32(const void* p) {
    unsigned r;
    asm("{ .reg .u64 t; cvta.to.shared.u64 t, %1; cvt.u32.u64 %0, t; }"
        : "=r"(r) : "l"(p));
    return r;
}

__global__ __launch_bounds__(THREADS)
void pprgo_tma_kernel(const float* __restrict__ emb,   // [N, 64]
                      const float* __restrict__ wei,   // [N, 32]
                      const int*   __restrict__ nei,   // [N, 32] int32
                      float* __restrict__ out,         // [N, 64]
                      int n_nodes)
{
    extern __shared__ char sm[];

    const int tid  = threadIdx.x;
    const int wid  = tid >> 5;
    const int lane = tid & 31;
    const int node = blockIdx.x * WARPS_PER_BLOCK + wid;

    char* mydata = sm + wid * NODE_BYTES;
    const unsigned mybar = smem_u32(sm) + SMEM_DATA + wid * 8;

    // per-warp mbarrier init (count=1), made visible to the async proxy
    if (lane == 0) {
        asm volatile("mbarrier.init.shared::cta.b64 [%0], 1;"
                     :: "r"(mybar) : "memory");
        asm volatile("fence.proxy.async.shared::cta;" ::: "memory");
    }
    __syncwarp();

    if (node >= n_nodes) return;   // grid is exact for N=200000, kept for safety

    const size_t row = (size_t)node * TOPK;

    // --- weight phase: lane k handles neighbor k ---
    float w  = wei[row + lane];
    float m  = (w != 0.0f) ? 1.0f : 0.0f;
    float s  = m;
    #pragma unroll
    for (int o = 16; o > 0; o >>= 1)
        s += __shfl_xor_sync(0xFFFFFFFFu, s, o);
    const float myw = m * (1.0f / (s + 1e-12f));

    const unsigned myidx = (unsigned)nei[row + lane];

    // --- gather phase: each lane TMA-copies its own neighbor row (256 B) ---
    if (lane == 0) {
        asm volatile("mbarrier.arrive.expect_tx.shared::cta.b64 _, [%0], %1;"
                     :: "r"(mybar), "r"(NODE_BYTES) : "memory");
    }
    __syncwarp();

    {
        const char* src = (const char*)emb + (size_t)myidx * ROW_BYTES;
        const unsigned dst = smem_u32(mydata) + lane * ROW_BYTES;
        asm volatile(
            "cp.async.bulk.shared::cta.global.mbarrier::complete_tx::bytes "
            "[%0], [%1], %2, [%3];"
            :: "r"(dst), "l"(src), "n"(ROW_BYTES), "r"(mybar) : "memory");
    }

    // wait for all 32 row copies (phase parity 0; barrier used once per block)
    asm volatile(
        "{\n\t"
        ".reg .pred P;\n\t"
        "WAIT_%=:\n\t"
        "mbarrier.try_wait.parity.acquire.cta.shared::cta.b64 P, [%0], 0, 0x989680;\n\t"
        "@!P bra WAIT_%=;\n\t"
        "}"
        :: "r"(mybar) : "memory");

    // --- consume: half-warp h owns row 2j+h; lane covers 4 floats ---
    const int half = lane >> 4;
    const int hl   = lane & 15;

    const float4* __restrict__ rows = reinterpret_cast<const float4*>(mydata);

    float4 acc = make_float4(0.f, 0.f, 0.f, 0.f);

    #pragma unroll
    for (int j = 0; j < TOPK / 2; ++j) {
        const int src = 2 * j + half;
        const float wj = __shfl_sync(0xFFFFFFFFu, myw, src);
        const float4 v = rows[src * (EMB / 4) + hl];   // LDS.128, conflict-free
        acc.x += wj * v.x;
        acc.y += wj * v.y;
        acc.z += wj * v.z;
        acc.w += wj * v.w;
    }

    // merge the two half-warp partials
    acc.x += __shfl_xor_sync(0xFFFFFFFFu, acc.x, 16);
    acc.y += __shfl_xor_sync(0xFFFFFFFFu, acc.y, 16);
    acc.z += __shfl_xor_sync(0xFFFFFFFFu, acc.z, 16);
    acc.w += __shfl_xor_sync(0xFFFFFFFFu, acc.w, 16);

    if (half == 0) {
        float4* __restrict__ o4p = reinterpret_cast<float4*>(out);
        o4p[(size_t)node * (EMB / 4) + hl] = acc;
    }
}

extern "C" void kernel_launch(void* const* d_in, const int* in_sizes, int n_in,
                              void* d_out, int out_size)
{
    const float* emb = (const float*)d_in[0];   // [N, 64]
    const float* wei = (const float*)d_in[1];   // [N, 32]
    const int*   nei = (const int*)d_in[2];     // [N, 32] int32
    float*       out = (float*)d_out;           // [N, 1, 64]

    const int n_nodes = in_sizes[1] / TOPK;     // 200000

    cudaFuncSetAttribute(pprgo_tma_kernel,
                         cudaFuncAttributeMaxDynamicSharedMemorySize, SMEM_TOTAL);

    const int blocks = (n_nodes + WARPS_PER_BLOCK - 1) / WARPS_PER_BLOCK; // 25000
    pprgo_tma_kernel<<<blocks, THREADS, SMEM_TOTAL>>>(emb, wei, nei, out, n_nodes);
}

// round 10
// speedup vs baseline: 1.9794x; 1.9794x over previous
#include <cuda_runtime.h>
#include <cstdint>

// PPRGo: out[n,:] = sum_k ( mask(wei[n,k]) / (sum_k mask + 1e-12) ) * emb_table[nei[n,k], :]
// N=200000, TOPK=32, EMB=64. nei is int32 on the wire.
//
// FINAL (R4 config, best of 9 rounds: 88.8us). One warp per node; gather
// uses LDG.128 covering TWO neighbor rows per instruction (lanes 0-15 ->
// row 2j, lanes 16-31 -> row 2j+1), default register budget (32 regs,
// ~88% occupancy). This sits at the L1tex wavefront floor (~128 phases/node
// demand+return), with L2 concurrently at ~77%.
// Closed axes (all regressed): cache hints (R3/R8), high-MLP via more regs
// (R5/R6), ballot-based weight math (R7), TMA/SMEM staging (R9).

static constexpr int TOPK = 32;
static constexpr int EMB  = 64;

__global__ __launch_bounds__(256)
void pprgo_kernel(const float* __restrict__ emb,   // [N, 64]
                  const float* __restrict__ wei,   // [N, 32]
                  const int*   __restrict__ nei,   // [N, 32] int32
                  float* __restrict__ out,         // [N, 64]
                  int n_nodes)
{
    const int warp_id = (blockIdx.x * blockDim.x + threadIdx.x) >> 5;
    const int lane    = threadIdx.x & 31;
    if (warp_id >= n_nodes) return;

    const size_t row = (size_t)warp_id * TOPK;

    // --- weight phase: lane k handles neighbor k ---
    float w  = wei[row + lane];
    float m  = (w != 0.0f) ? 1.0f : 0.0f;
    float s  = m;
    #pragma unroll
    for (int o = 16; o > 0; o >>= 1)
        s += __shfl_xor_sync(0xFFFFFFFFu, s, o);
    const float myw = m * (1.0f / (s + 1e-12f));

    const int myidx = nei[row + lane];

    // --- gather phase: half-warp h owns row 2j+h; lane covers 4 floats ---
    const int half = lane >> 4;          // 0 or 1
    const int hl   = lane & 15;          // position within half-warp

    const float4* __restrict__ e4 = reinterpret_cast<const float4*>(emb);

    float4 acc = make_float4(0.f, 0.f, 0.f, 0.f);

    #pragma unroll
    for (int j = 0; j < TOPK / 2; j += 8) {
        int src0 = 2 * (j + 0) + half;
        int src1 = 2 * (j + 1) + half;
        int src2 = 2 * (j + 2) + half;
        int src3 = 2 * (j + 3) + half;
        int src4 = 2 * (j + 4) + half;
        int src5 = 2 * (j + 5) + half;
        int src6 = 2 * (j + 6) + half;
        int src7 = 2 * (j + 7) + half;

        // 32-bit element offsets: max index 200000*16+15 < 2^32
        unsigned o0 = (unsigned)__shfl_sync(0xFFFFFFFFu, myidx, src0) * (EMB/4) + hl;
        unsigned o1 = (unsigned)__shfl_sync(0xFFFFFFFFu, myidx, src1) * (EMB/4) + hl;
        unsigned o2 = (unsigned)__shfl_sync(0xFFFFFFFFu, myidx, src2) * (EMB/4) + hl;
        unsigned o3 = (unsigned)__shfl_sync(0xFFFFFFFFu, myidx, src3) * (EMB/4) + hl;
        unsigned o4 = (unsigned)__shfl_sync(0xFFFFFFFFu, myidx, src4) * (EMB/4) + hl;
        unsigned o5 = (unsigned)__shfl_sync(0xFFFFFFFFu, myidx, src5) * (EMB/4) + hl;
        unsigned o6 = (unsigned)__shfl_sync(0xFFFFFFFFu, myidx, src6) * (EMB/4) + hl;
        unsigned o7 = (unsigned)__shfl_sync(0xFFFFFFFFu, myidx, src7) * (EMB/4) + hl;

        float w0 = __shfl_sync(0xFFFFFFFFu, myw, src0);
        float w1 = __shfl_sync(0xFFFFFFFFu, myw, src1);
        float w2 = __shfl_sync(0xFFFFFFFFu, myw, src2);
        float w3 = __shfl_sync(0xFFFFFFFFu, myw, src3);
        float w4 = __shfl_sync(0xFFFFFFFFu, myw, src4);
        float w5 = __shfl_sync(0xFFFFFFFFu, myw, src5);
        float w6 = __shfl_sync(0xFFFFFFFFu, myw, src6);
        float w7 = __shfl_sync(0xFFFFFFFFu, myw, src7);

        // 8 independent LDG.128; each covers 2 neighbor rows
        float4 v0 = e4[o0];
        float4 v1 = e4[o1];
        float4 v2 = e4[o2];
        float4 v3 = e4[o3];
        float4 v4 = e4[o4];
        float4 v5 = e4[o5];
        float4 v6 = e4[o6];
        float4 v7 = e4[o7];

        acc.x += w0 * v0.x; acc.y += w0 * v0.y; acc.z += w0 * v0.z; acc.w += w0 * v0.w;
        acc.x += w1 * v1.x; acc.y += w1 * v1.y; acc.z += w1 * v1.z; acc.w += w1 * v1.w;
        acc.x += w2 * v2.x; acc.y += w2 * v2.y; acc.z += w2 * v2.z; acc.w += w2 * v2.w;
        acc.x += w3 * v3.x; acc.y += w3 * v3.y; acc.z += w3 * v3.z; acc.w += w3 * v3.w;
        acc.x += w4 * v4.x; acc.y += w4 * v4.y; acc.z += w4 * v4.z; acc.w += w4 * v4.w;
        acc.x += w5 * v5.x; acc.y += w5 * v5.y; acc.z += w5 * v5.z; acc.w += w5 * v5.w;
        acc.x += w6 * v6.x; acc.y += w6 * v6.y; acc.z += w6 * v6.z; acc.w += w6 * v6.w;
        acc.x += w7 * v7.x; acc.y += w7 * v7.y; acc.z += w7 * v7.z; acc.w += w7 * v7.w;
    }

    // merge the two half-warp partials
    acc.x += __shfl_xor_sync(0xFFFFFFFFu, acc.x, 16);
    acc.y += __shfl_xor_sync(0xFFFFFFFFu, acc.y, 16);
    acc.z += __shfl_xor_sync(0xFFFFFFFFu, acc.z, 16);
    acc.w += __shfl_xor_sync(0xFFFFFFFFu, acc.w, 16);

    if (half == 0) {
        float4* __restrict__ o4p = reinterpret_cast<float4*>(out);
        o4p[(size_t)warp_id * (EMB/4) + hl] = acc;
    }
}

extern "C" void kernel_launch(void* const* d_in, const int* in_sizes, int n_in,
                              void* d_out, int out_size)
{
    const float* emb = (const float*)d_in[0];   // [N, 64]
    const float* wei = (const float*)d_in[1];   // [N, 32]
    const int*   nei = (const int*)d_in[2];     // [N, 32] int32
    float*       out = (float*)d_out;           // [N, 1, 64]

    const int n_nodes = in_sizes[1] / TOPK;     // 200000

    const int threads = 256;                    // 8 warps/block
    const int warps_per_block = threads / 32;
    const int blocks = (n_nodes + warps_per_block - 1) / warps_per_block;

    pprgo_kernel<<<blocks, threads>>>(emb, wei, nei, out, n_nodes);
}